// round 6
// baseline (speedup 1.0000x reference)
#include <cuda_runtime.h>
#include <cuda_fp16.h>

#define N_I 500000
#define N_H 200000
#define F_I 32
#define F_H 16
#define EF  8
#define E1  2000000
#define E2  2000000

#define TPB 256
#define ZB  489                      // zero blocks: ceil(125000 float4 / 256)
#define HB  782                      // pre_house blocks: ceil(200000/256)
#define PIB 3907                     // pre_indivi blocks: ceil(500000/128)
#define E1B 7813                     // edge_h2i blocks: ceil(E1/256)
#define E2B 7813                     // edge_i2i blocks: ceil(E2/256)
#define MREG (PIB + E1B)             // 11720 (pre_i : edge_h2i interleaved 1:2)
#define MAIN_BLOCKS (ZB + HB + MREG)

#define STRIDE_I 33
#define STRIDE_H 17

// Packed per-source-node record, 32 B (one L2 sector):
//  [0..3]=y as 8x fp16 pairs, [4]=z fp32, [5..7] pad
__device__ __align__(32) float g_rec_h[(size_t)N_H * 8];
__device__ __align__(32) float g_rec_i[(size_t)N_I * 8];

// Progress counters (zero-initialized; reset at end of k3 for graph replay)
__device__ int g_cnt_z;
__device__ int g_cnt_h;
__device__ int g_cnt_e2;

__device__ __forceinline__ float pack2h(float a, float b) {
    __half2 h = __floats2half2_rn(a, b);
    return __uint_as_float(*reinterpret_cast<unsigned*>(&h));
}

__device__ __forceinline__ void spin_until(volatile int* p, int target) {
    while (*p < target) __nanosleep(64);
}

// ==========================================================================
// Edge message body: msg = ea[e].y[src] + z[src]; atomic add to out[dst].
// ==========================================================================
__device__ __forceinline__ void
edge_body(const float* __restrict__ ea, const int* __restrict__ src,
          const int* __restrict__ dst, const float* __restrict__ rec,
          float* __restrict__ out, int e)
{
    int s = __ldg(src + e);
    int d = __ldg(dst + e);

    const float4* ar = reinterpret_cast<const float4*>(ea + (size_t)e * EF);
    float4 a0 = __ldg(ar);
    float4 a1 = __ldg(ar + 1);

    float4 v = __ldg(reinterpret_cast<const float4*>(rec + (size_t)s * 8));
    float  z = __ldg(rec + (size_t)s * 8 + 4);     // same 32B sector

    float2 f01 = __half22float2(*reinterpret_cast<__half2*>(&v.x));
    float2 f23 = __half22float2(*reinterpret_cast<__half2*>(&v.y));
    float2 f45 = __half22float2(*reinterpret_cast<__half2*>(&v.z));
    float2 f67 = __half22float2(*reinterpret_cast<__half2*>(&v.w));

    float m = z;
    m = fmaf(a0.x, f01.x, m);
    m = fmaf(a0.y, f01.y, m);
    m = fmaf(a0.z, f23.x, m);
    m = fmaf(a0.w, f23.y, m);
    m = fmaf(a1.x, f45.x, m);
    m = fmaf(a1.y, f45.y, m);
    m = fmaf(a1.z, f67.x, m);
    m = fmaf(a1.w, f67.y, m);

    atomicAdd(out + d, m);
}

// ==========================================================================
// Mega kernel: [zero out][pre_house][pre_indivi 1 : edge_h2i 2 interleaved]
// ==========================================================================
__global__ void __launch_bounds__(TPB)
main_kernel(const float* __restrict__ x_indivi,
            const float* __restrict__ x_house,
            const float* __restrict__ W_edge_i,  // [F_I, EF]
            const float* __restrict__ b_edge_i,  // [F_I]
            const float* __restrict__ W_edge_h,  // [F_H, EF]
            const float* __restrict__ b_edge_h,  // [F_H]
            const float* __restrict__ W_root_h,  // [1, F_I]
            const float* __restrict__ W_root_i,  // [1, F_I]
            const float* __restrict__ bias_h,    // [1]
            const float* __restrict__ bias_i,    // [1]
            const float* __restrict__ ea1,
            const int*   __restrict__ src1,
            const int*   __restrict__ dst1,
            float* __restrict__ out)
{
    __shared__ float sx[256 * STRIDE_H];   // 17.4 KB (union for both pre roles)
    __shared__ float sW[F_I * EF];
    __shared__ float sb[F_I];
    __shared__ float sWr[F_I];
    __shared__ float sbias;

    int t = threadIdx.x;
    unsigned b = blockIdx.x;

    // ---------------- zero region ----------------
    if (b < ZB) {
        int i = b * TPB + t;
        if (i < N_I / 4)
            reinterpret_cast<float4*>(out)[i] = make_float4(0.f, 0.f, 0.f, 0.f);
        __threadfence();
        __syncthreads();
        if (t == 0) atomicAdd(&g_cnt_z, 1);
        return;
    }
    b -= ZB;

    // ---------------- pre_house region ----------------
    if (b < HB) {
        if (t < F_H * EF) sW[t] = W_edge_h[t];
        if (t < F_H)      sb[t] = b_edge_h[t];

        int base = b * 256;
        const float4* x4 = reinterpret_cast<const float4*>(x_house);
        long gbase = (long)base * (F_H / 4);
        long gmax  = (long)N_H * (F_H / 4);
#pragma unroll
        for (int i = 0; i < 4; i++) {
            long gidx = gbase + t + i * 256;
            if (gidx < gmax) {
                float4 v = x4[gidx];
                int loc = t + i * 256;
                int row = loc >> 2;
                int col = loc & 3;
                float* p = sx + row * STRIDE_H + col * 4;
                p[0] = v.x; p[1] = v.y; p[2] = v.z; p[3] = v.w;
            }
        }
        __syncthreads();

        int n = base + t;
        if (n < N_H) {
            const float* xr = sx + t * STRIDE_H;
            float y[EF];
#pragma unroll
            for (int k = 0; k < EF; k++) y[k] = 0.f;
            float z = 0.f;
#pragma unroll
            for (int f = 0; f < F_H; f++) {
                float xf = xr[f];
#pragma unroll
                for (int k = 0; k < EF; k++) y[k] = fmaf(xf, sW[f*EF + k], y[k]);
                z = fmaf(xf, sb[f], z);
            }
            float4* ro = reinterpret_cast<float4*>(g_rec_h + (size_t)n * 8);
            ro[0] = make_float4(pack2h(y[0], y[1]), pack2h(y[2], y[3]),
                                pack2h(y[4], y[5]), pack2h(y[6], y[7]));
            ro[1] = make_float4(z, 0.f, 0.f, 0.f);
        }
        __threadfence();
        __syncthreads();
        if (t == 0) atomicAdd(&g_cnt_h, 1);
        return;
    }
    b -= HB;

    // ---------------- interleaved region: pre_i (r%3==0) : edge_h2i ------
    int q = b / 3, m = b % 3;
    bool is_pre = (m == 0) && (q < PIB);

    if (!is_pre) {
        // edge_h2i block
        int pre_before = (q < PIB) ? (q + 1) : PIB;   // m>0 here when q<PIB
        if (m == 0) pre_before = PIB;                  // q>=PIB, m==0
        int eb = b - pre_before;
        // wait for out zeroed + rec_h ready (both early in dispatch order)
        if (t == 0) {
            spin_until(&g_cnt_z, ZB);
            spin_until(&g_cnt_h, HB);
        }
        __syncthreads();
        int e = eb * TPB + t;
        if (e < E1)
            edge_body(ea1, src1, dst1, g_rec_h, out, e);
        return;
    }

    // pre_indivi block: 128 nodes, 2 threads per node (feature halves)
    sW[t] = W_edge_i[t];
    if (t < F_I) {
        sb[t]  = b_edge_i[t];
        sWr[t] = W_root_h[t] + W_root_i[t];
    }
    if (t == 0) sbias = bias_h[0] + bias_i[0];

    int base = q * 128;
    const float4* x4 = reinterpret_cast<const float4*>(x_indivi);
    long gbase = (long)base * (F_I / 4);
    long gmax  = (long)N_I * (F_I / 4);
#pragma unroll
    for (int i = 0; i < 4; i++) {
        long gidx = gbase + t + i * 256;
        if (gidx < gmax) {
            float4 v = x4[gidx];
            int loc = t + i * 256;
            int row = loc >> 3;                 // 8 float4 per row
            int col = loc & 7;
            float* p = sx + row * STRIDE_I + col * 4;
            p[0] = v.x; p[1] = v.y; p[2] = v.z; p[3] = v.w;
        }
    }
    __syncthreads();

    int warp = t >> 5, lane = t & 31;
    int node_local = warp * 16 + (lane & 15);   // 8 warps x 16 nodes = 128
    int half = lane >> 4;                        // 0: feats 0-15, 1: 16-31
    int f0 = half * 16;

    const float* xr = sx + node_local * STRIDE_I + f0;
    float y[EF];
#pragma unroll
    for (int k = 0; k < EF; k++) y[k] = 0.f;
    float z = 0.f, root = 0.f;
#pragma unroll
    for (int j = 0; j < 16; j++) {
        float xf = xr[j];
        int f = f0 + j;
#pragma unroll
        for (int k = 0; k < EF; k++) y[k] = fmaf(xf, sW[f*EF + k], y[k]);
        z    = fmaf(xf, sb[f],  z);
        root = fmaf(xf, sWr[f], root);
    }
    // combine feature halves (lane l += lane l+16)
#pragma unroll
    for (int k = 0; k < EF; k++) y[k] += __shfl_down_sync(0xffffffffu, y[k], 16);
    z    += __shfl_down_sync(0xffffffffu, z, 16);
    root += __shfl_down_sync(0xffffffffu, root, 16);

    int n = base + node_local;
    if (half == 0 && n < N_I) {
        float4* ro = reinterpret_cast<float4*>(g_rec_i + (size_t)n * 8);
        ro[0] = make_float4(pack2h(y[0], y[1]), pack2h(y[2], y[3]),
                            pack2h(y[4], y[5]), pack2h(y[6], y[7]));
        ro[1] = make_float4(z, 0.f, 0.f, 0.f);
    }
    // root atomicAdd needs out zeroed (zero blocks are earliest; spin is ~free)
    if (t == 0) spin_until(&g_cnt_z, ZB);
    __syncthreads();
    if (half == 0 && n < N_I)
        atomicAdd(out + n, root + sbias);
}

// ==========================================================================
// K3: edge_i2i scatter (launch boundary guarantees rec_i complete);
//     last block resets counters for the next graph replay.
// ==========================================================================
__global__ void __launch_bounds__(TPB)
k3_edge_i(const float* __restrict__ ea2,
          const int*   __restrict__ src2,
          const int*   __restrict__ dst2,
          float* __restrict__ out)
{
    int e = blockIdx.x * TPB + threadIdx.x;
    if (e < E2)
        edge_body(ea2, src2, dst2, g_rec_i, out, e);
    __syncthreads();
    if (threadIdx.x == 0) {
        int done = atomicAdd(&g_cnt_e2, 1);
        if (done == E2B - 1) {
            g_cnt_z = 0;
            g_cnt_h = 0;
            g_cnt_e2 = 0;
        }
    }
}

// ==========================================================================
extern "C" void kernel_launch(void* const* d_in, const int* in_sizes, int n_in,
                              void* d_out, int out_size)
{
    const float* x_indivi      = (const float*)d_in[0];
    const float* x_house       = (const float*)d_in[1];
    const float* edge_attr_h2i = (const float*)d_in[2];
    const float* edge_attr_i2i = (const float*)d_in[3];
    const float* W_edge_h2i    = (const float*)d_in[4];
    const float* b_edge_h2i    = (const float*)d_in[5];
    const float* W_edge_i2i    = (const float*)d_in[6];
    const float* b_edge_i2i    = (const float*)d_in[7];
    const float* W_root_h2i    = (const float*)d_in[8];
    const float* bias_h2i      = (const float*)d_in[9];
    const float* W_root_i2i    = (const float*)d_in[10];
    const float* bias_i2i      = (const float*)d_in[11];
    const int*   src_h2i       = (const int*)d_in[12];
    const int*   dst_h2i       = (const int*)d_in[13];
    const int*   src_i2i       = (const int*)d_in[14];
    const int*   dst_i2i       = (const int*)d_in[15];
    float* out = (float*)d_out;

    main_kernel<<<MAIN_BLOCKS, TPB>>>(
        x_indivi, x_house, W_edge_i2i, b_edge_i2i, W_edge_h2i, b_edge_h2i,
        W_root_h2i, W_root_i2i, bias_h2i, bias_i2i,
        edge_attr_h2i, src_h2i, dst_h2i, out);

    k3_edge_i<<<E2B, TPB>>>(
        edge_attr_i2i, src_i2i, dst_i2i, out);
}

// round 7
// speedup vs baseline: 1.1040x; 1.1040x over previous
#include <cuda_runtime.h>
#include <cuda_fp16.h>

#define N_I 500000
#define N_H 200000
#define F_I 32
#define F_H 16
#define EF  8
#define E1  2000000
#define E2  2000000

// ---- pre kernel geometry ----
#define TILE_I   128          // indivi nodes per tile (1024 float4)
#define TILES_PER_BLK_I 8
#define NTILE_I  3907         // ceil(N_I/128)
#define PREB_I   489          // ceil(3907/8)
#define TILE_H   256          // house nodes per tile (1024 float4)
#define TILES_PER_BLK_H 4
#define NTILE_H  782          // ceil(N_H/256)
#define PREB_H   196          // ceil(782/4)
#define STRIDE_I 36           // floats per staged indivi row (16B-aligned rows)
#define STRIDE_H 20           // floats per staged house row
#define SBUF_FLOATS 5248      // >= max(128*36=4608, 256*20=5120)

// ---- edge kernel geometry (2 edges per thread, 512-edge chunks) ----
#define EB1 3907              // ceil(E1/512)
#define EB2 3907              // ceil(E2/512)

// Packed per-source-node record, 32 B (one L2 sector):
//  [0..3]=y as 8x fp16 pairs, [4]=z fp32, [5..7] pad
__device__ __align__(32) float g_rec_h[(size_t)N_H * 8];
__device__ __align__(32) float g_rec_i[(size_t)N_I * 8];

__device__ __forceinline__ float pack2h(float a, float b) {
    __half2 h = __floats2half2_rn(a, b);
    return __uint_as_float(*reinterpret_cast<unsigned*>(&h));
}

__device__ __forceinline__ unsigned smem_u32(const void* p) {
    return (unsigned)__cvta_generic_to_shared(p);
}
__device__ __forceinline__ void cp16(unsigned dst, const void* src) {
    asm volatile("cp.async.ca.shared.global [%0], [%1], 16;\n" :: "r"(dst), "l"(src));
}
__device__ __forceinline__ void cp_commit() {
    asm volatile("cp.async.commit_group;\n" ::: "memory");
}
__device__ __forceinline__ void cp_wait1() {
    asm volatile("cp.async.wait_group 1;\n" ::: "memory");
}
__device__ __forceinline__ void cp_wait0() {
    asm volatile("cp.async.wait_group 0;\n" ::: "memory");
}

// ==========================================================================
// Pre kernel: cp.async double-buffered multi-tile pipeline.
//   blocks [0, PREB_I): indivi — rec_i + out[n] = root (direct store)
//   blocks [PREB_I, +PREB_H): house — rec_h
// ==========================================================================
__global__ void __launch_bounds__(256)
pre_kernel(const float* __restrict__ x_indivi,
           const float* __restrict__ x_house,
           const float* __restrict__ W_edge_i,  // [F_I, EF]
           const float* __restrict__ b_edge_i,  // [F_I]
           const float* __restrict__ W_edge_h,  // [F_H, EF]
           const float* __restrict__ b_edge_h,  // [F_H]
           const float* __restrict__ W_root_h,  // [1, F_I]
           const float* __restrict__ W_root_i,  // [1, F_I]
           const float* __restrict__ bias_h,    // [1]
           const float* __restrict__ bias_i,    // [1]
           float* __restrict__ out)
{
    __shared__ float sbuf[2][SBUF_FLOATS];
    __shared__ float sW[F_I * EF];
    __shared__ float sb[F_I];
    __shared__ float sWr[F_I];
    __shared__ float sbias;

    int t = threadIdx.x;

    if (blockIdx.x < PREB_I) {
        // ---------------- indivi region ----------------
        sW[t] = W_edge_i[t];                    // 256 == F_I*EF
        if (t < F_I) {
            sb[t]  = b_edge_i[t];
            sWr[t] = W_root_h[t] + W_root_i[t];
        }
        if (t == 0) sbias = bias_h[0] + bias_i[0];

        int tile0 = blockIdx.x * TILES_PER_BLK_I;
        const long gmax = (long)N_I * (F_I / 4);        // float4 count
        const float4* x4 = reinterpret_cast<const float4*>(x_indivi);

        // issue tile j into buffer buf
        auto issue_i = [&](int j, int buf) {
            long base_f4 = (long)(tile0 + j) * TILE_I * (F_I / 4);
            unsigned sb32 = smem_u32(sbuf[buf]);
#pragma unroll
            for (int i = 0; i < 4; i++) {
                int  loc  = t + i * 256;
                long gidx = base_f4 + loc;
                if (gidx < gmax) {
                    int row = loc >> 3, col = loc & 7;
                    cp16(sb32 + (row * STRIDE_I + col * 4) * 4, x4 + gidx);
                }
            }
            cp_commit();
        };

        int ntiles = NTILE_I - tile0;
        if (ntiles > TILES_PER_BLK_I) ntiles = TILES_PER_BLK_I;
        if (ntiles <= 0) return;

        issue_i(0, 0);
        __syncthreads();   // sW/sb ready (cheap, once)

        int warp = t >> 5, lane = t & 31;
        int node_local = warp * 16 + (lane & 15);
        int half = lane >> 4;
        int f0 = half * 16;

        for (int tt = 0; tt < ntiles; tt++) {
            if (tt + 1 < ntiles) { issue_i(tt + 1, (tt + 1) & 1); cp_wait1(); }
            else                 { cp_wait0(); }
            __syncthreads();

            const float* xr = sbuf[tt & 1] + node_local * STRIDE_I + f0;
            float y[EF];
#pragma unroll
            for (int k = 0; k < EF; k++) y[k] = 0.f;
            float z = 0.f, root = 0.f;
#pragma unroll
            for (int j = 0; j < 16; j++) {
                float xf = xr[j];
                int f = f0 + j;
#pragma unroll
                for (int k = 0; k < EF; k++) y[k] = fmaf(xf, sW[f*EF + k], y[k]);
                z    = fmaf(xf, sb[f],  z);
                root = fmaf(xf, sWr[f], root);
            }
#pragma unroll
            for (int k = 0; k < EF; k++)
                y[k] += __shfl_down_sync(0xffffffffu, y[k], 16);
            z    += __shfl_down_sync(0xffffffffu, z, 16);
            root += __shfl_down_sync(0xffffffffu, root, 16);

            int n = (tile0 + tt) * TILE_I + node_local;
            if (half == 0 && n < N_I) {
                float4* ro = reinterpret_cast<float4*>(g_rec_i + (size_t)n * 8);
                ro[0] = make_float4(pack2h(y[0], y[1]), pack2h(y[2], y[3]),
                                    pack2h(y[4], y[5]), pack2h(y[6], y[7]));
                ro[1] = make_float4(z, 0.f, 0.f, 0.f);
                out[n] = root + sbias;
            }
            __syncthreads();
        }
    } else {
        // ---------------- house region ----------------
        if (t < F_H * EF) sW[t] = W_edge_h[t];
        if (t < F_H)      sb[t] = b_edge_h[t];

        int tile0 = (blockIdx.x - PREB_I) * TILES_PER_BLK_H;
        const long gmax = (long)N_H * (F_H / 4);
        const float4* x4 = reinterpret_cast<const float4*>(x_house);

        auto issue_h = [&](int j, int buf) {
            long base_f4 = (long)(tile0 + j) * TILE_H * (F_H / 4);
            unsigned sb32 = smem_u32(sbuf[buf]);
#pragma unroll
            for (int i = 0; i < 4; i++) {
                int  loc  = t + i * 256;
                long gidx = base_f4 + loc;
                if (gidx < gmax) {
                    int row = loc >> 2, col = loc & 3;
                    cp16(sb32 + (row * STRIDE_H + col * 4) * 4, x4 + gidx);
                }
            }
            cp_commit();
        };

        int ntiles = NTILE_H - tile0;
        if (ntiles > TILES_PER_BLK_H) ntiles = TILES_PER_BLK_H;
        if (ntiles <= 0) return;

        issue_h(0, 0);
        __syncthreads();

        for (int tt = 0; tt < ntiles; tt++) {
            if (tt + 1 < ntiles) { issue_h(tt + 1, (tt + 1) & 1); cp_wait1(); }
            else                 { cp_wait0(); }
            __syncthreads();

            int n = (tile0 + tt) * TILE_H + t;
            if (n < N_H) {
                const float* xr = sbuf[tt & 1] + t * STRIDE_H;
                float y[EF];
#pragma unroll
                for (int k = 0; k < EF; k++) y[k] = 0.f;
                float z = 0.f;
#pragma unroll
                for (int f = 0; f < F_H; f++) {
                    float xf = xr[f];
#pragma unroll
                    for (int k = 0; k < EF; k++) y[k] = fmaf(xf, sW[f*EF + k], y[k]);
                    z = fmaf(xf, sb[f], z);
                }
                float4* ro = reinterpret_cast<float4*>(g_rec_h + (size_t)n * 8);
                ro[0] = make_float4(pack2h(y[0], y[1]), pack2h(y[2], y[3]),
                                    pack2h(y[4], y[5]), pack2h(y[6], y[7]));
                ro[1] = make_float4(z, 0.f, 0.f, 0.f);
            }
            __syncthreads();
        }
    }
}

// ==========================================================================
// Edge kernel: both relations, 2 edges per thread (512-edge block chunks).
// ==========================================================================
__device__ __forceinline__ float
msg_of(float4 a0, float4 a1, float4 v, float z)
{
    float2 f01 = __half22float2(*reinterpret_cast<__half2*>(&v.x));
    float2 f23 = __half22float2(*reinterpret_cast<__half2*>(&v.y));
    float2 f45 = __half22float2(*reinterpret_cast<__half2*>(&v.z));
    float2 f67 = __half22float2(*reinterpret_cast<__half2*>(&v.w));
    float m = z;
    m = fmaf(a0.x, f01.x, m);
    m = fmaf(a0.y, f01.y, m);
    m = fmaf(a0.z, f23.x, m);
    m = fmaf(a0.w, f23.y, m);
    m = fmaf(a1.x, f45.x, m);
    m = fmaf(a1.y, f45.y, m);
    m = fmaf(a1.z, f67.x, m);
    m = fmaf(a1.w, f67.y, m);
    return m;
}

__device__ __forceinline__ void
edge_pair(const float* __restrict__ ea, const int* __restrict__ src,
          const int* __restrict__ dst, const float* __restrict__ rec,
          float* __restrict__ out, int chunk, int t, int Emax)
{
    int e0 = chunk * 512 + t;
    int e1 = e0 + 256;
    bool v0 = e0 < Emax, v1 = e1 < Emax;

    int s0 = 0, d0 = 0, s1 = 0, d1 = 0;
    if (v0) { s0 = __ldg(src + e0); d0 = __ldg(dst + e0); }
    if (v1) { s1 = __ldg(src + e1); d1 = __ldg(dst + e1); }

    float4 a00 = {}, a01 = {}, a10 = {}, a11 = {};
    if (v0) {
        const float4* ar = reinterpret_cast<const float4*>(ea + (size_t)e0 * EF);
        a00 = __ldg(ar); a01 = __ldg(ar + 1);
    }
    if (v1) {
        const float4* ar = reinterpret_cast<const float4*>(ea + (size_t)e1 * EF);
        a10 = __ldg(ar); a11 = __ldg(ar + 1);
    }

    float4 r0 = {}, r1 = {};
    float  z0 = 0.f, z1 = 0.f;
    if (v0) {
        r0 = __ldg(reinterpret_cast<const float4*>(rec + (size_t)s0 * 8));
        z0 = __ldg(rec + (size_t)s0 * 8 + 4);
    }
    if (v1) {
        r1 = __ldg(reinterpret_cast<const float4*>(rec + (size_t)s1 * 8));
        z1 = __ldg(rec + (size_t)s1 * 8 + 4);
    }

    if (v0) atomicAdd(out + d0, msg_of(a00, a01, r0, z0));
    if (v1) atomicAdd(out + d1, msg_of(a10, a11, r1, z1));
}

__global__ void __launch_bounds__(256)
edge_kernel(const float* __restrict__ ea1,
            const int*   __restrict__ src1,
            const int*   __restrict__ dst1,
            const float* __restrict__ ea2,
            const int*   __restrict__ src2,
            const int*   __restrict__ dst2,
            float* __restrict__ out)
{
    int t = threadIdx.x;
    if (blockIdx.x < EB1) {
        edge_pair(ea1, src1, dst1, g_rec_h, out, blockIdx.x, t, E1);
    } else {
        edge_pair(ea2, src2, dst2, g_rec_i, out, blockIdx.x - EB1, t, E2);
    }
}

// ==========================================================================
extern "C" void kernel_launch(void* const* d_in, const int* in_sizes, int n_in,
                              void* d_out, int out_size)
{
    const float* x_indivi      = (const float*)d_in[0];
    const float* x_house       = (const float*)d_in[1];
    const float* edge_attr_h2i = (const float*)d_in[2];
    const float* edge_attr_i2i = (const float*)d_in[3];
    const float* W_edge_h2i    = (const float*)d_in[4];
    const float* b_edge_h2i    = (const float*)d_in[5];
    const float* W_edge_i2i    = (const float*)d_in[6];
    const float* b_edge_i2i    = (const float*)d_in[7];
    const float* W_root_h2i    = (const float*)d_in[8];
    const float* bias_h2i      = (const float*)d_in[9];
    const float* W_root_i2i    = (const float*)d_in[10];
    const float* bias_i2i      = (const float*)d_in[11];
    const int*   src_h2i       = (const int*)d_in[12];
    const int*   dst_h2i       = (const int*)d_in[13];
    const int*   src_i2i       = (const int*)d_in[14];
    const int*   dst_i2i       = (const int*)d_in[15];
    float* out = (float*)d_out;

    pre_kernel<<<PREB_I + PREB_H, 256>>>(
        x_indivi, x_house, W_edge_i2i, b_edge_i2i, W_edge_h2i, b_edge_h2i,
        W_root_h2i, W_root_i2i, bias_h2i, bias_i2i, out);

    edge_kernel<<<EB1 + EB2, 256>>>(
        edge_attr_h2i, src_h2i, dst_h2i,
        edge_attr_i2i, src_i2i, dst_i2i, out);
}